// round 7
// baseline (speedup 1.0000x reference)
#include <cuda_runtime.h>

#define NMAX  1536
#define TPB   256
#define EPT   6          // strided elements per thread (NMAX / TPB)
#define NITER 20

__device__ int g_maxdeg;

// ---------------------------------------------------------------------------
// Kernel 1 (pre): per-group offset (redundant prefix sum) + degree count
// -> global max degree via atomicMax.
// ---------------------------------------------------------------------------
__global__ void __launch_bounds__(512)
pre_kernel(const int* __restrict__ sizes,
           const int* __restrict__ edges,
           int N, int B) {
    __shared__ int cnt[NMAX];
    __shared__ int red[16];
    __shared__ int s_off;

    int g = blockIdx.x;
    int t = threadIdx.x;
    int lane = t & 31, wid = t >> 5;

    int part = 0;
    for (int i = t; i < g; i += 512) part += sizes[i];
#pragma unroll
    for (int d = 16; d; d >>= 1) part += __shfl_xor_sync(0xffffffffu, part, d);
    if (lane == 0) red[wid] = part;
    __syncthreads();
    if (t == 0) {
        int s = 0;
#pragma unroll
        for (int w = 0; w < 16; ++w) s += red[w];
        s_off = s;
    }
    int n = sizes[g];
    __syncthreads();
    int off = s_off;

    for (int i = t; i < n; i += 512)
        cnt[i] = (i == 0 || i == n - 1) ? 1 : 2;
    __syncthreads();

    const int2* e2 = (const int2*)edges;
    int reBase = (N - B) + off;
    for (int i = t; i < n; i += 512) {
        int2 e = e2[reBase + i];
        atomicAdd(&cnt[e.x - off], 1);
        atomicAdd(&cnt[e.y - off], 1);
    }
    __syncthreads();

    int m = 0;
    for (int i = t; i < n; i += 512) m = max(m, cnt[i]);
#pragma unroll
    for (int d = 16; d; d >>= 1) m = max(m, __shfl_xor_sync(0xffffffffu, m, d));
    if (lane == 0) red[wid] = m;
    __syncthreads();
    if (t == 0) {
        int mm = red[0];
#pragma unroll
        for (int w = 1; w < 16; ++w) mm = max(mm, red[w]);
        atomicMax(&g_maxdeg, mm);
    }
}

// ---------------------------------------------------------------------------
// Kernel 2 (main): fused per-group solve. Delta-scatter, 2 barriers/iter,
// shuffle-based chain coupling (warp-boundary smem only), zero-delta atomic
// skip, Michelot sparsemax.
// ---------------------------------------------------------------------------
__global__ void __launch_bounds__(TPB, 3)
main_kernel(const float* __restrict__ x,
            const int*   __restrict__ sizes,
            const int*   __restrict__ edges,
            float*       __restrict__ out,
            int N, int B) {
    __shared__ float ys[NMAX];
    __shared__ float racc[NMAX];
    __shared__ float uc[NMAX];        // only warp-boundary slots hot
    __shared__ float red_s[8];
    __shared__ int   red_c[8];
    __shared__ int   red_i[8];
    __shared__ float s_tau;
    __shared__ int   s_cnt;
    __shared__ int   s_off;

    int g = blockIdx.x;
    int t = threadIdx.x;
    int lane = t & 31, wid = t >> 5;

    // offset[g] = sum of sizes[0..g)  (redundant recompute; L2-resident)
    {
        int part = 0;
        for (int i = t; i < g; i += TPB) part += sizes[i];
#pragma unroll
        for (int d = 16; d; d >>= 1) part += __shfl_xor_sync(0xffffffffu, part, d);
        if (lane == 0) red_i[wid] = part;
        __syncthreads();
        if (t == 0) {
            int s = 0;
#pragma unroll
            for (int w = 0; w < 8; ++w) s += red_i[w];
            s_off = s;
        }
    }
    int n = sizes[g];
    __syncthreads();
    int off = s_off;
    int reBase = (N - B) + off;

    float xr[EPT], ur[EPT], ucv[EPT], yv[EPT];
    int   ea[EPT], eb[EPT];

    const int2* e2 = (const int2*)edges;
#pragma unroll
    for (int j = 0; j < EPT; ++j) {
        int i = t + j * TPB;
        bool a = (j < 2) || (i < n);   // first 512 slots always active (n>=512)
        if (a) {
            xr[j] = x[off + i];
            int2 e = e2[reBase + i];
            ea[j] = e.x - off;
            eb[j] = e.y - off;
            ys[i]   = xr[j];
            racc[i] = 0.0f;
        } else {
            xr[j] = 0.0f; ea[j] = 0; eb[j] = 0;
            if (i < NMAX) { ys[i] = 0.0f; racc[i] = 0.0f; }
        }
        if (i < NMAX) uc[i] = 0.0f;
        yv[j]  = xr[j];
        ur[j]  = 0.0f;
        ucv[j] = 0.0f;
    }
    float step = 0.5f / (float)g_maxdeg;
    __syncthreads();

    // ---- 20 iterations, 2 barriers each ----
    for (int it = 0; it < NITER; ++it) {
        // Phase P: dual updates from current y (yv regs + ys smem).
#pragma unroll
        for (int j = 0; j < EPT; ++j) {
            int i = t + j * TPB;
            float ynext = __shfl_down_sync(0xffffffffu, yv[j], 1);
            if (lane == 31 && i + 1 < NMAX) ynext = ys[i + 1];
            bool a = (j < 2) || (i < n);
            if (a) {
                if (i < n - 1) {
                    float nu = ucv[j] + step * (yv[j] - ynext);
                    ucv[j] = fminf(1.0f, fmaxf(-1.0f, nu));
                }
                if (lane == 31) uc[i] = ucv[j];
                float ya = ys[ea[j]], yb = ys[eb[j]];
                float nu = ur[j] + step * (ya - yb);
                nu = fminf(1.0f, fmaxf(-1.0f, nu));
                float d = nu - ur[j];
                ur[j] = nu;
                if (d != 0.0f) {
                    atomicAdd(&racc[ea[j]], -d);
                    atomicAdd(&racc[eb[j]],  d);
                }
            }
        }
        __syncthreads();
        // Phase R: rebuild y = x + uc[i-1] - uc[i] + racc[i].
#pragma unroll
        for (int j = 0; j < EPT; ++j) {
            int i = t + j * TPB;
            float up = __shfl_up_sync(0xffffffffu, ucv[j], 1);
            if (lane == 0 && i > 0) up = uc[i - 1];
            bool a = (j < 2) || (i < n);
            if (a) {
                float v = xr[j] + racc[i];
                if (i > 0)     v += up;
                if (i < n - 1) v -= ucv[j];
                yv[j] = v;
                ys[i] = v;
            }
        }
        __syncthreads();
    }

    // ---- sparsemax via Michelot (exact, no sort) ----
    {
        float s = 0.0f;
#pragma unroll
        for (int j = 0; j < EPT; ++j) {
            int i = t + j * TPB;
            if ((j < 2) || (i < n)) s += yv[j];
        }
#pragma unroll
        for (int d = 16; d; d >>= 1) s += __shfl_xor_sync(0xffffffffu, s, d);
        if (lane == 0) red_s[wid] = s;
        __syncthreads();
        if (t == 0) {
            float ss = 0.0f;
#pragma unroll
            for (int w = 0; w < 8; ++w) ss += red_s[w];
            s_tau = (ss - 1.0f) / (float)n;
            s_cnt = n;
        }
        __syncthreads();
    }

    float tau = s_tau;
    int prev_cnt = s_cnt;

    for (int itm = 0; itm < 64; ++itm) {
        float s = 0.0f;
        int   c = 0;
#pragma unroll
        for (int j = 0; j < EPT; ++j) {
            int i = t + j * TPB;
            bool a = (j < 2) || (i < n);
            if (a && yv[j] > tau) { s += yv[j]; ++c; }
        }
#pragma unroll
        for (int d = 16; d; d >>= 1) {
            s += __shfl_xor_sync(0xffffffffu, s, d);
            c += __shfl_xor_sync(0xffffffffu, c, d);
        }
        if (lane == 0) { red_s[wid] = s; red_c[wid] = c; }
        __syncthreads();
        if (t == 0) {
            float ss = 0.0f; int cc = 0;
#pragma unroll
            for (int w = 0; w < 8; ++w) { ss += red_s[w]; cc += red_c[w]; }
            s_tau = (ss - 1.0f) / (float)cc;
            s_cnt = cc;
        }
        __syncthreads();
        tau = s_tau;
        int cnt_now = s_cnt;
        if (cnt_now == prev_cnt) break;
        prev_cnt = cnt_now;
    }

    float scale = (float)n;
#pragma unroll
    for (int j = 0; j < EPT; ++j) {
        int i = t + j * TPB;
        if ((j < 2) || (i < n))
            out[off + i] = fmaxf(yv[j] - tau, 0.0f) * scale;
    }
}

// ---------------------------------------------------------------------------
extern "C" void kernel_launch(void* const* d_in, const int* in_sizes, int n_in,
                              void* d_out, int out_size) {
    const float* x     = (const float*)d_in[0];
    const int*   sizes = (const int*)  d_in[1];
    const int*   edges = (const int*)  d_in[2];
    float*       out   = (float*)d_out;
    int N = in_sizes[0];
    int B = in_sizes[1];

    pre_kernel<<<B, 512>>>(sizes, edges, N, B);
    main_kernel<<<B, TPB>>>(x, sizes, edges, out, N, B);
}

// round 8
// speedup vs baseline: 1.2361x; 1.2361x over previous
#include <cuda_runtime.h>

#define NMAX  1536
#define TPB   256
#define EPT   6          // strided elements per thread (NMAX / TPB)
#define NITER 20

__device__ int g_maxdeg;

// ---------------------------------------------------------------------------
// Kernel 1 (pre): per-group offset (redundant prefix sum) + degree count
// -> global max degree via atomicMax.
// ---------------------------------------------------------------------------
__global__ void __launch_bounds__(512)
pre_kernel(const int* __restrict__ sizes,
           const int* __restrict__ edges,
           int N, int B) {
    __shared__ int cnt[NMAX];
    __shared__ int red[16];
    __shared__ int s_off;

    int g = blockIdx.x;
    int t = threadIdx.x;
    int lane = t & 31, wid = t >> 5;

    int part = 0;
    for (int i = t; i < g; i += 512) part += sizes[i];
#pragma unroll
    for (int d = 16; d; d >>= 1) part += __shfl_xor_sync(0xffffffffu, part, d);
    if (lane == 0) red[wid] = part;
    __syncthreads();
    if (t == 0) {
        int s = 0;
#pragma unroll
        for (int w = 0; w < 16; ++w) s += red[w];
        s_off = s;
    }
    int n = sizes[g];
    __syncthreads();
    int off = s_off;

    for (int i = t; i < n; i += 512)
        cnt[i] = (i == 0 || i == n - 1) ? 1 : 2;
    __syncthreads();

    const int2* e2 = (const int2*)edges;
    int reBase = (N - B) + off;
    for (int i = t; i < n; i += 512) {
        int2 e = e2[reBase + i];
        atomicAdd(&cnt[e.x - off], 1);
        atomicAdd(&cnt[e.y - off], 1);
    }
    __syncthreads();

    int m = 0;
    for (int i = t; i < n; i += 512) m = max(m, cnt[i]);
#pragma unroll
    for (int d = 16; d; d >>= 1) m = max(m, __shfl_xor_sync(0xffffffffu, m, d));
    if (lane == 0) red[wid] = m;
    __syncthreads();
    if (t == 0) {
        int mm = red[0];
#pragma unroll
        for (int w = 1; w < 16; ++w) mm = max(mm, red[w]);
        atomicMax(&g_maxdeg, mm);
    }
}

// ---------------------------------------------------------------------------
// Kernel 2 (main): fused per-group solve.
// Random-edge contributions via unique-slot stores (ev[4*node+slot]) +
// float4 gather; overflow (deg>4) via rare delta-atomics into ovf[].
// ---------------------------------------------------------------------------
__global__ void __launch_bounds__(TPB, 3)
main_kernel(const float* __restrict__ x,
            const int*   __restrict__ sizes,
            const int*   __restrict__ edges,
            float*       __restrict__ out,
            int N, int B) {
    __shared__ float ys[NMAX];
    __shared__ float uc[NMAX];
    __shared__ float ev[4 * NMAX];     // 4 contribution slots per node
    __shared__ float ovf[NMAX];        // overflow accumulator (deg>4), aliased as int cnt during setup
    __shared__ float red_s[8];
    __shared__ int   red_c[8];
    __shared__ int   red_i[8];
    __shared__ float s_tau;
    __shared__ int   s_cnt;
    __shared__ int   s_off;

    int g = blockIdx.x;
    int t = threadIdx.x;
    int lane = t & 31, wid = t >> 5;

    // offset[g] = sum of sizes[0..g)  (redundant recompute; L2-resident)
    {
        int part = 0;
        for (int i = t; i < g; i += TPB) part += sizes[i];
#pragma unroll
        for (int d = 16; d; d >>= 1) part += __shfl_xor_sync(0xffffffffu, part, d);
        if (lane == 0) red_i[wid] = part;
        __syncthreads();
        if (t == 0) {
            int s = 0;
#pragma unroll
            for (int w = 0; w < 8; ++w) s += red_i[w];
            s_off = s;
        }
    }
    int n = sizes[g];
    __syncthreads();
    int off = s_off;
    int reBase = (N - B) + off;

    float xr[EPT], ur[EPT], ucv[EPT], yv[EPT];
    int   ea[EPT], eb[EPT];
    unsigned sl[EPT];   // packed slot sub-indices: pa | (pb<<8)

    int* cnt = (int*)ovf;

    const int2* e2 = (const int2*)edges;
#pragma unroll
    for (int j = 0; j < EPT; ++j) {
        int i = t + j * TPB;
        bool a = (j < 2) || (i < n);   // first 512 slots always active (n>=512)
        if (a) {
            xr[j] = x[off + i];
            int2 e = e2[reBase + i];
            ea[j] = e.x - off;
            eb[j] = e.y - off;
            ys[i] = xr[j];
        } else {
            xr[j] = 0.0f; ea[j] = 0; eb[j] = 0;
            if (i < NMAX) ys[i] = 0.0f;
        }
        if (i < NMAX) { uc[i] = 0.0f; cnt[i] = 0; }
        yv[j]  = xr[j];
        ur[j]  = 0.0f;
        ucv[j] = 0.0f;
    }
#pragma unroll
    for (int k = 0; k < 4 * EPT; ++k)
        ev[t + k * TPB] = 0.0f;
    float step = 0.5f / (float)g_maxdeg;
    __syncthreads();

    // claim per-endpoint slots
#pragma unroll
    for (int j = 0; j < EPT; ++j) {
        int i = t + j * TPB;
        bool a = (j < 2) || (i < n);
        if (a) {
            int pa = atomicAdd(&cnt[ea[j]], 1);
            int pb = atomicAdd(&cnt[eb[j]], 1);
            sl[j] = (unsigned)min(pa, 255) | ((unsigned)min(pb, 255) << 8);
        } else sl[j] = 0;
    }
    __syncthreads();
    // re-init ovf as float zero
#pragma unroll
    for (int j = 0; j < EPT; ++j) {
        int i = t + j * TPB;
        if (i < NMAX) ovf[i] = 0.0f;
    }
    __syncthreads();

    // ---- 20 iterations, 2 barriers each ----
    for (int it = 0; it < NITER; ++it) {
        // Phase P: dual updates from current y; publish contributions.
#pragma unroll
        for (int j = 0; j < EPT; ++j) {
            int i = t + j * TPB;
            bool a = (j < 2) || (i < n);
            if (a) {
                if (i < n - 1) {
                    float nu = ucv[j] + step * (yv[j] - ys[i + 1]);
                    nu = fminf(1.0f, fmaxf(-1.0f, nu));
                    ucv[j] = nu;
                    uc[i] = nu;
                }
                float ya = ys[ea[j]], yb = ys[eb[j]];
                float nu = ur[j] + step * (ya - yb);
                nu = fminf(1.0f, fmaxf(-1.0f, nu));
                unsigned s = sl[j];
                int pa = (int)(s & 255u), pb = (int)(s >> 8);
                if (pa < 4) ev[4 * ea[j] + pa] = -nu;
                else        atomicAdd(&ovf[ea[j]], -(nu - ur[j]));
                if (pb < 4) ev[4 * eb[j] + pb] =  nu;
                else        atomicAdd(&ovf[eb[j]],  (nu - ur[j]));
                ur[j] = nu;
            }
        }
        __syncthreads();
        // Phase R: rebuild y = x + uc[i-1] - uc[i] + sum(slots) + ovf.
#pragma unroll
        for (int j = 0; j < EPT; ++j) {
            int i = t + j * TPB;
            bool a = (j < 2) || (i < n);
            if (a) {
                float4 e4 = *(const float4*)&ev[4 * i];
                float v = xr[j] + ((e4.x + e4.y) + (e4.z + e4.w)) + ovf[i];
                if (i > 0)     v += uc[i - 1];
                if (i < n - 1) v -= ucv[j];
                yv[j] = v;
                ys[i] = v;
            }
        }
        __syncthreads();
    }

    // ---- sparsemax via Michelot (exact, no sort) ----
    {
        float s = 0.0f;
#pragma unroll
        for (int j = 0; j < EPT; ++j) {
            int i = t + j * TPB;
            if ((j < 2) || (i < n)) s += yv[j];
        }
#pragma unroll
        for (int d = 16; d; d >>= 1) s += __shfl_xor_sync(0xffffffffu, s, d);
        if (lane == 0) red_s[wid] = s;
        __syncthreads();
        if (t == 0) {
            float ss = 0.0f;
#pragma unroll
            for (int w = 0; w < 8; ++w) ss += red_s[w];
            s_tau = (ss - 1.0f) / (float)n;
            s_cnt = n;
        }
        __syncthreads();
    }

    float tau = s_tau;
    int prev_cnt = s_cnt;

    for (int itm = 0; itm < 64; ++itm) {
        float s = 0.0f;
        int   c = 0;
#pragma unroll
        for (int j = 0; j < EPT; ++j) {
            int i = t + j * TPB;
            bool a = (j < 2) || (i < n);
            if (a && yv[j] > tau) { s += yv[j]; ++c; }
        }
#pragma unroll
        for (int d = 16; d; d >>= 1) {
            s += __shfl_xor_sync(0xffffffffu, s, d);
            c += __shfl_xor_sync(0xffffffffu, c, d);
        }
        if (lane == 0) { red_s[wid] = s; red_c[wid] = c; }
        __syncthreads();
        if (t == 0) {
            float ss = 0.0f; int cc = 0;
#pragma unroll
            for (int w = 0; w < 8; ++w) { ss += red_s[w]; cc += red_c[w]; }
            s_tau = (ss - 1.0f) / (float)cc;
            s_cnt = cc;
        }
        __syncthreads();
        tau = s_tau;
        int cnt_now = s_cnt;
        if (cnt_now == prev_cnt) break;
        prev_cnt = cnt_now;
    }

    float scale = (float)n;
#pragma unroll
    for (int j = 0; j < EPT; ++j) {
        int i = t + j * TPB;
        if ((j < 2) || (i < n))
            out[off + i] = fmaxf(yv[j] - tau, 0.0f) * scale;
    }
}

// ---------------------------------------------------------------------------
extern "C" void kernel_launch(void* const* d_in, const int* in_sizes, int n_in,
                              void* d_out, int out_size) {
    const float* x     = (const float*)d_in[0];
    const int*   sizes = (const int*)  d_in[1];
    const int*   edges = (const int*)  d_in[2];
    float*       out   = (float*)d_out;
    int N = in_sizes[0];
    int B = in_sizes[1];

    pre_kernel<<<B, 512>>>(sizes, edges, N, B);
    main_kernel<<<B, TPB>>>(x, sizes, edges, out, N, B);
}